// round 3
// baseline (speedup 1.0000x reference)
#include <cuda_runtime.h>
#include <math.h>

// TwoLayerNetwork: ConstantCurrentLIFEncoder -> LIFCell -> LILinearCell, T=32,
// then max over timesteps and log_softmax.
//
// Constants: DT*TAU_MEM_INV = 0.1 (decay 0.9), DT*TAU_SYN_INV = 0.2 (decay 0.8),
// V_TH = 1.0.
//
// EXACT per-row fast path (proof): v_enc follows v' = 0.9 v + 0.1 x from 0, so
// v_enc <= max_j x_j for all t. A spike needs v_enc > 1.0, so if ALL pixels of
// a row are <= 1.0 that row never spikes anywhere downstream: v_out stays 0 and
// the answer is log_softmax(zeros) = -log(10).
//
// Two-kernel split so the register-heavy general simulator doesn't throttle the
// memory-bound scan:
//   scan_kernel: warp/row, float4 loads, low regs, writes -log(10) + hot flag.
//   sim_kernel:  full verified dynamics, runs only for flagged (hot) rows.

#define NT 32
#define NPL 25   // neurons per lane (25*32 = 800 >= 784)
#define NB 4096

__device__ unsigned g_hot[NB];   // per-row "may spike" flag

// ---------------- Kernel A: scan + constant write ----------------
__global__ __launch_bounds__(256) void scan_kernel(
    const float* __restrict__ image,   // [4096, 784]
    float* __restrict__ out)           // [4096, 10]
{
    const int lane = threadIdx.x & 31;
    const int b = blockIdx.x * 8 + (threadIdx.x >> 5);

    const float4* x4 = (const float4*)(image + (size_t)b * 784);  // 196 vec4

    float m = 0.0f;
#pragma unroll
    for (int i = 0; i < 6; i++) {
        const float4 v = __ldg(&x4[lane + 32 * i]);
        m = fmaxf(m, fmaxf(fmaxf(v.x, v.y), fmaxf(v.z, v.w)));
    }
    if (lane < 4) {   // 196 = 6*32 + 4
        const float4 v = __ldg(&x4[lane + 192]);
        m = fmaxf(m, fmaxf(fmaxf(v.x, v.y), fmaxf(v.z, v.w)));
    }

    const unsigned hot = __ballot_sync(0xffffffffu, m > 1.0f);
    if (lane < 10)
        out[(size_t)b * 10 + lane] = -2.302585093f;  // log_softmax(zeros)
    if (lane == 0)
        g_hot[b] = hot;   // nonzero iff some pixel > 1.0
}

// ---------------- Kernel B: full simulator for hot rows ----------------
__global__ __launch_bounds__(128) void sim_kernel(
    const float* __restrict__ image,   // [4096, 784]
    const float* __restrict__ W,       // [10, 784]
    float* __restrict__ out)           // [4096, 10]
{
    const int lane = threadIdx.x & 31;
    const int b = blockIdx.x * 4 + (threadIdx.x >> 5);

    if (g_hot[b] == 0u) return;   // provably spike-free: constant already written

    const float* x = image + (size_t)b * 784;

    float xs[NPL];   // 0.1 * x
    float ve[NPL];   // encoder membrane
    float v0[NPL];   // hidden membrane
    float i0[NPL];   // hidden synaptic current
#pragma unroll
    for (int i = 0; i < NPL; i++) {
        const int j = lane + 32 * i;
        xs[i] = (j < 784) ? 0.1f * __ldg(&x[j]) : 0.0f;
        ve[i] = 0.0f; v0[i] = 0.0f; i0[i] = 0.0f;
    }

    float v_out = 0.0f, i_out = 0.0f, vmax = -INFINITY;

#pragma unroll 1
    for (int t = 0; t < NT; t++) {
        unsigned tmask = 0u;
#pragma unroll
        for (int i = 0; i < NPL; i++) {
            // encoder LIF step
            float v = fmaf(ve[i], 0.9f, xs[i]);
            const bool pe = (v > 1.0f);
            const float zef = pe ? 1.0f : 0.0f;
            ve[i] = pe ? 0.0f : v;
            // hidden LIF step (reads old v0, i0)
            const float vd = fmaf(v0[i], 0.9f, 0.1f * i0[i]);
            const bool p0 = (vd > 1.0f);
            v0[i] = p0 ? 0.0f : vd;
            i0[i] = fmaf(i0[i], 0.8f, zef);
            if (p0) tmask |= (1u << i);
        }

        // s[k] = sum_j z0[j] * W[k, j]; zero on spike-free steps.
        float s = 0.0f;
        if (__any_sync(0xffffffffu, tmask != 0u)) {
            float acc[10];
#pragma unroll
            for (int k = 0; k < 10; k++) acc[k] = 0.0f;
            unsigned m = tmask;
            while (m) {
                const int i = __ffs(m) - 1;
                m &= (m - 1u);
                const int j = lane + 32 * i;
#pragma unroll
                for (int k = 0; k < 10; k++)
                    acc[k] += __ldg(&W[k * 784 + j]);
            }
#pragma unroll
            for (int k = 0; k < 10; k++) {
#pragma unroll
                for (int off = 16; off; off >>= 1)
                    acc[k] += __shfl_xor_sync(0xffffffffu, acc[k], off);
            }
            s = acc[0];
#pragma unroll
            for (int k = 1; k < 10; k++) s = (lane == k) ? acc[k] : s;
        }

        const float i_jump = i_out + s;
        v_out = fmaf(v_out, 0.9f, 0.1f * i_jump);
        i_out = 0.8f * i_jump;
        vmax = fmaxf(vmax, v_out);
    }

    // log_softmax over the 10 classes held by lanes 0..9
    const float v = (lane < 10) ? vmax : -INFINITY;
    float mred = v;
#pragma unroll
    for (int off = 16; off; off >>= 1)
        mred = fmaxf(mred, __shfl_xor_sync(0xffffffffu, mred, off));
    float e = (lane < 10) ? expf(v - mred) : 0.0f;
    float se = e;
#pragma unroll
    for (int off = 16; off; off >>= 1)
        se += __shfl_xor_sync(0xffffffffu, se, off);

    if (lane < 10)
        out[(size_t)b * 10 + lane] = v - mred - logf(se);
}

extern "C" void kernel_launch(void* const* d_in, const int* in_sizes, int n_in,
                              void* d_out, int out_size) {
    const float* image = (const float*)d_in[0];  // [4096,1,28,28] fp32
    const float* W     = (const float*)d_in[1];  // [10,784] fp32
    float* out         = (float*)d_out;          // [4096,10] fp32
    (void)in_sizes; (void)n_in; (void)out_size;

    scan_kernel<<<512, 256>>>(image, out);
    sim_kernel<<<1024, 128>>>(image, W, out);
}

// round 4
// speedup vs baseline: 1.2917x; 1.2917x over previous
#include <cuda_runtime.h>
#include <math.h>

// TwoLayerNetwork: ConstantCurrentLIFEncoder -> LIFCell -> LILinearCell, T=32,
// then max over timesteps and log_softmax.
//
// Constants: DT*TAU_MEM_INV = 0.1 (decay 0.9), DT*TAU_SYN_INV = 0.2 (decay 0.8),
// V_TH = 1.0.
//
// EXACT per-row fast path (proof): v_enc follows v' = 0.9 v + 0.1 x from 0, so
// v_enc <= max_j x_j for all t. A spike needs v_enc > 1.0, so if ALL pixels of
// a row are <= 1.0 that row never spikes anywhere downstream: v_out stays 0 and
// the answer is log_softmax(zeros) = -log(10).
//
// Single kernel (R3 showed a second launch costs ~5us by itself). Warp-per-row.
// Fast path: float4 row-max scan (low regs, high MLP). Hot rows reload scalar
// in the sim layout and run the full verified dynamics; register cap via
// __launch_bounds__ spills only the hot path, which cold rows never touch.

#define NT 32
#define NPL 25   // neurons per lane (25*32 = 800 >= 784)

__global__ __launch_bounds__(256, 6) void snn_kernel(
    const float* __restrict__ image,   // [4096, 784]
    const float* __restrict__ W,       // [10, 784]
    float* __restrict__ out)           // [4096, 10]
{
    const int lane = threadIdx.x & 31;
    const int b = blockIdx.x * 8 + (threadIdx.x >> 5);

    const float* x = image + (size_t)b * 784;
    const float4* x4 = (const float4*)x;   // 196 vec4 per row

    // ---- vectorized row-max scan ----
    float m = 0.0f;
#pragma unroll
    for (int i = 0; i < 6; i++) {
        const float4 v = __ldg(&x4[lane + 32 * i]);
        m = fmaxf(m, fmaxf(fmaxf(v.x, v.y), fmaxf(v.z, v.w)));
    }
    if (lane < 4) {   // 196 = 6*32 + 4
        const float4 v = __ldg(&x4[lane + 192]);
        m = fmaxf(m, fmaxf(fmaxf(v.x, v.y), fmaxf(v.z, v.w)));
    }

    // Fast path: row provably spike-free -> log_softmax(zeros) = -log(10).
    if (!__any_sync(0xffffffffu, m > 1.0f)) {
        if (lane < 10)
            out[(size_t)b * 10 + lane] = -2.302585093f;
        return;
    }

    // ---- Full general simulation (bit-exact verified R1 path) ----
    // Reload in the lane-strided sim layout (L2-hot). Spills here are fine:
    // only rows that can actually spike pay for them.
    float xs[NPL];   // 0.1 * x
    float ve[NPL];   // encoder membrane
    float v0[NPL];   // hidden membrane
    float i0[NPL];   // hidden synaptic current
#pragma unroll
    for (int i = 0; i < NPL; i++) {
        const int j = lane + 32 * i;
        xs[i] = (j < 784) ? 0.1f * __ldg(&x[j]) : 0.0f;
        ve[i] = 0.0f; v0[i] = 0.0f; i0[i] = 0.0f;
    }

    float v_out = 0.0f, i_out = 0.0f, vmax = -INFINITY;

#pragma unroll 1
    for (int t = 0; t < NT; t++) {
        unsigned tmask = 0u;
#pragma unroll
        for (int i = 0; i < NPL; i++) {
            // encoder LIF step
            float v = fmaf(ve[i], 0.9f, xs[i]);
            const bool pe = (v > 1.0f);
            const float zef = pe ? 1.0f : 0.0f;
            ve[i] = pe ? 0.0f : v;
            // hidden LIF step (reads old v0, i0)
            const float vd = fmaf(v0[i], 0.9f, 0.1f * i0[i]);
            const bool p0 = (vd > 1.0f);
            v0[i] = p0 ? 0.0f : vd;
            i0[i] = fmaf(i0[i], 0.8f, zef);
            if (p0) tmask |= (1u << i);
        }

        // s[k] = sum_j z0[j] * W[k, j]; zero on spike-free steps.
        float s = 0.0f;
        if (__any_sync(0xffffffffu, tmask != 0u)) {
            float acc[10];
#pragma unroll
            for (int k = 0; k < 10; k++) acc[k] = 0.0f;
            unsigned mm = tmask;
            while (mm) {
                const int i = __ffs(mm) - 1;
                mm &= (mm - 1u);
                const int j = lane + 32 * i;
#pragma unroll
                for (int k = 0; k < 10; k++)
                    acc[k] += __ldg(&W[k * 784 + j]);
            }
#pragma unroll
            for (int k = 0; k < 10; k++) {
#pragma unroll
                for (int off = 16; off; off >>= 1)
                    acc[k] += __shfl_xor_sync(0xffffffffu, acc[k], off);
            }
            s = acc[0];
#pragma unroll
            for (int k = 1; k < 10; k++) s = (lane == k) ? acc[k] : s;
        }

        const float i_jump = i_out + s;
        v_out = fmaf(v_out, 0.9f, 0.1f * i_jump);
        i_out = 0.8f * i_jump;
        vmax = fmaxf(vmax, v_out);
    }

    // log_softmax over the 10 classes held by lanes 0..9
    const float v = (lane < 10) ? vmax : -INFINITY;
    float mred = v;
#pragma unroll
    for (int off = 16; off; off >>= 1)
        mred = fmaxf(mred, __shfl_xor_sync(0xffffffffu, mred, off));
    float e = (lane < 10) ? expf(v - mred) : 0.0f;
    float se = e;
#pragma unroll
    for (int off = 16; off; off >>= 1)
        se += __shfl_xor_sync(0xffffffffu, se, off);

    if (lane < 10)
        out[(size_t)b * 10 + lane] = v - mred - logf(se);
}

extern "C" void kernel_launch(void* const* d_in, const int* in_sizes, int n_in,
                              void* d_out, int out_size) {
    const float* image = (const float*)d_in[0];  // [4096,1,28,28] fp32
    const float* W     = (const float*)d_in[1];  // [10,784] fp32
    float* out         = (float*)d_out;          // [4096,10] fp32
    (void)in_sizes; (void)n_in; (void)out_size;

    snn_kernel<<<512, 256>>>(image, W, out);
}

// round 5
// speedup vs baseline: 1.3478x; 1.0435x over previous
#include <cuda_runtime.h>
#include <math.h>

// TwoLayerNetwork: ConstantCurrentLIFEncoder -> LIFCell -> LILinearCell, T=32,
// then max over timesteps and log_softmax.
//
// Constants: DT*TAU_MEM_INV = 0.1 (decay 0.9), DT*TAU_SYN_INV = 0.2 (decay 0.8),
// V_TH = 1.0.
//
// EXACT per-row fast path (proof): v_enc follows v' = 0.9 v + 0.1 x from 0, so
// v_enc <= max_j x_j for all t. A spike needs v_enc > 1.0, so if ALL pixels of
// a row are <= 1.0 that row never spikes anywhere downstream: v_out stays 0 and
// the answer is log_softmax(zeros) = -log(10).
//
// Measured model (R2..R4): ~5us fixed launch/ramp floor + ~1.5us memory body.
// This round: write the constant BEFORE the scan (store retires during the
// DRAM wait; hot rows overwrite it in program order), best launch shape
// (1024 x 128), vec4 scan, low-reg fast path.

#define NT 32
#define NPL 25   // neurons per lane (25*32 = 800 >= 784)

__global__ __launch_bounds__(128) void snn_kernel(
    const float* __restrict__ image,   // [4096, 784]
    const float* __restrict__ W,       // [10, 784]
    float* __restrict__ out)           // [4096, 10]
{
    const int lane = threadIdx.x & 31;
    const int b = blockIdx.x * 4 + (threadIdx.x >> 5);

    // Unconditional early write of the spike-free answer. Hot rows (rare,
    // exceptional case) overwrite below; same thread, program order => final
    // value is always correct.
    if (lane < 10)
        out[(size_t)b * 10 + lane] = -2.302585093f;  // log_softmax(zeros)

    const float* x = image + (size_t)b * 784;
    const float4* x4 = (const float4*)x;   // 196 vec4 per row

    // ---- vectorized row-max scan ----
    float m = 0.0f;
#pragma unroll
    for (int i = 0; i < 6; i++) {
        const float4 v = __ldg(&x4[lane + 32 * i]);
        m = fmaxf(m, fmaxf(fmaxf(v.x, v.y), fmaxf(v.z, v.w)));
    }
    if (lane < 4) {   // 196 = 6*32 + 4
        const float4 v = __ldg(&x4[lane + 192]);
        m = fmaxf(m, fmaxf(fmaxf(v.x, v.y), fmaxf(v.z, v.w)));
    }

    // Row provably spike-free -> constant already written, done.
    if (!__any_sync(0xffffffffu, m > 1.0f))
        return;

    // ---- Full general simulation (bit-exact verified R1 path) ----
    // Only rows that can actually spike reach here; reload in sim layout
    // (L2-hot). Register/spill cost is paid only on this path.
    float xs[NPL];   // 0.1 * x
    float ve[NPL];   // encoder membrane
    float v0[NPL];   // hidden membrane
    float i0[NPL];   // hidden synaptic current
#pragma unroll
    for (int i = 0; i < NPL; i++) {
        const int j = lane + 32 * i;
        xs[i] = (j < 784) ? 0.1f * __ldg(&x[j]) : 0.0f;
        ve[i] = 0.0f; v0[i] = 0.0f; i0[i] = 0.0f;
    }

    float v_out = 0.0f, i_out = 0.0f, vmax = -INFINITY;

#pragma unroll 1
    for (int t = 0; t < NT; t++) {
        unsigned tmask = 0u;
#pragma unroll
        for (int i = 0; i < NPL; i++) {
            // encoder LIF step
            float v = fmaf(ve[i], 0.9f, xs[i]);
            const bool pe = (v > 1.0f);
            const float zef = pe ? 1.0f : 0.0f;
            ve[i] = pe ? 0.0f : v;
            // hidden LIF step (reads old v0, i0)
            const float vd = fmaf(v0[i], 0.9f, 0.1f * i0[i]);
            const bool p0 = (vd > 1.0f);
            v0[i] = p0 ? 0.0f : vd;
            i0[i] = fmaf(i0[i], 0.8f, zef);
            if (p0) tmask |= (1u << i);
        }

        // s[k] = sum_j z0[j] * W[k, j]; zero on spike-free steps.
        float s = 0.0f;
        if (__any_sync(0xffffffffu, tmask != 0u)) {
            float acc[10];
#pragma unroll
            for (int k = 0; k < 10; k++) acc[k] = 0.0f;
            unsigned mm = tmask;
            while (mm) {
                const int i = __ffs(mm) - 1;
                mm &= (mm - 1u);
                const int j = lane + 32 * i;
#pragma unroll
                for (int k = 0; k < 10; k++)
                    acc[k] += __ldg(&W[k * 784 + j]);
            }
#pragma unroll
            for (int k = 0; k < 10; k++) {
#pragma unroll
                for (int off = 16; off; off >>= 1)
                    acc[k] += __shfl_xor_sync(0xffffffffu, acc[k], off);
            }
            s = acc[0];
#pragma unroll
            for (int k = 1; k < 10; k++) s = (lane == k) ? acc[k] : s;
        }

        const float i_jump = i_out + s;
        v_out = fmaf(v_out, 0.9f, 0.1f * i_jump);
        i_out = 0.8f * i_jump;
        vmax = fmaxf(vmax, v_out);
    }

    // log_softmax over the 10 classes held by lanes 0..9
    const float v = (lane < 10) ? vmax : -INFINITY;
    float mred = v;
#pragma unroll
    for (int off = 16; off; off >>= 1)
        mred = fmaxf(mred, __shfl_xor_sync(0xffffffffu, mred, off));
    float e = (lane < 10) ? expf(v - mred) : 0.0f;
    float se = e;
#pragma unroll
    for (int off = 16; off; off >>= 1)
        se += __shfl_xor_sync(0xffffffffu, se, off);

    if (lane < 10)
        out[(size_t)b * 10 + lane] = v - mred - logf(se);
}

extern "C" void kernel_launch(void* const* d_in, const int* in_sizes, int n_in,
                              void* d_out, int out_size) {
    const float* image = (const float*)d_in[0];  // [4096,1,28,28] fp32
    const float* W     = (const float*)d_in[1];  // [10,784] fp32
    float* out         = (float*)d_out;          // [4096,10] fp32
    (void)in_sizes; (void)n_in; (void)out_size;

    snn_kernel<<<1024, 128>>>(image, W, out);
}